// round 14
// baseline (speedup 1.0000x reference)
#include <cuda_runtime.h>
#include <cuda_bf16.h>
#include <cuda_fp16.h>
#include <cstdint>

#define B 2
#define S 2048
#define HID 2048
#define H 16
#define KVH 4
#define D 128
#define GROUPS (H / KVH)
#define MROWS (B * S)          // 4096
#define ND_Q (H * D)           // 2048
#define ND_KV (KVH * D)        // 512
#define QK_SCALE 0.08838834764831845f

// ---------------- scratch (no allocations allowed) ----------------
__device__ __align__(16) __half g_xa_h[MROWS * HID];      // x as fp16
__device__ __align__(16) __half g_oa_h[MROWS * ND_Q];     // attention out as fp16
__device__ __align__(16) __half g_wqT_h[ND_Q * HID];
__device__ __align__(16) __half g_wkT_h[ND_KV * HID];
__device__ __align__(16) __half g_wvT_h[ND_KV * HID];
__device__ __align__(16) __half g_woT_h[HID * ND_Q];
// attention operand layouts (fp16)
__device__ __align__(16) __half g_qs_h[B * H * S * D];    // [b][h][s][d], scaled+rope
__device__ __align__(16) __half g_ks_h[B * KVH * S * D];  // [b][kvh][s][d], rope
__device__ __align__(16) __half g_vt_h[B * KVH * D * S];  // [b][kvh][d][s]

// ---------------- helpers ----------------
__device__ __forceinline__ uint32_t smem_u32(const void* p) {
    uint32_t a;
    asm("{ .reg .u64 t; cvta.to.shared.u64 t, %1; cvt.u32.u64 %0, t; }" : "=r"(a) : "l"(p));
    return a;
}
__device__ __forceinline__ void cp_async16(uint32_t saddr, const void* gaddr) {
    asm volatile("cp.async.cg.shared.global [%0], [%1], 16;" :: "r"(saddr), "l"(gaddr)
                 : "memory");
}
__device__ __forceinline__ void cp_commit() {
    asm volatile("cp.async.commit_group;" ::: "memory");
}
template <int N>
__device__ __forceinline__ void cp_wait() {
    asm volatile("cp.async.wait_group %0;" :: "n"(N) : "memory");
}
__device__ __forceinline__ void ldsm_x4(uint32_t* r, uint32_t addr) {
    asm volatile("ldmatrix.sync.aligned.m8n8.x4.shared.b16 {%0,%1,%2,%3}, [%4];"
                 : "=r"(r[0]), "=r"(r[1]), "=r"(r[2]), "=r"(r[3]) : "r"(addr));
}
__device__ __forceinline__ void mma_f16(float* c, const uint32_t* a, const uint32_t* b) {
    asm volatile(
        "mma.sync.aligned.m16n8k16.row.col.f32.f16.f16.f32 "
        "{%0,%1,%2,%3}, {%4,%5,%6,%7}, {%8,%9}, {%0,%1,%2,%3};"
        : "+f"(c[0]), "+f"(c[1]), "+f"(c[2]), "+f"(c[3])
        : "r"(a[0]), "r"(a[1]), "r"(a[2]), "r"(a[3]), "r"(b[0]), "r"(b[1]));
}

// ---------------- fp32 -> fp16 convert ----------------
__global__ void to_f16(const float4* __restrict__ src, __half2* __restrict__ dst, int n4) {
    int i = blockIdx.x * blockDim.x + threadIdx.x;
    if (i >= n4) return;
    float4 v = src[i];
    dst[2 * i]     = __floats2half2_rn(v.x, v.y);
    dst[2 * i + 1] = __floats2half2_rn(v.z, v.w);
}

// ---------------- transpose: W[K,N] fp32 -> T[N,K] fp16 ----------------
__global__ void transpose_h(const float* __restrict__ W, __half* __restrict__ Th,
                            int K, int N) {
    __shared__ float t[32][33];
    int k0 = blockIdx.y * 32, n0 = blockIdx.x * 32;
    int tx = threadIdx.x, ty = threadIdx.y;
#pragma unroll
    for (int j = 0; j < 4; j++)
        t[ty + j * 8][tx] = W[(size_t)(k0 + ty + j * 8) * N + n0 + tx];
    __syncthreads();
#pragma unroll
    for (int j = 0; j < 4; j++) {
        int n = n0 + ty + j * 8;
        Th[(size_t)n * K + k0 + tx] = __float2half_rn(t[tx][ty + j * 8]);
    }
}

// ---------------- fp16 tensor-core GEMM with fused epilogues ----------------
// MODE 0: C fp32 row-major            (wo projection)
// MODE 1: RoPE + QK_SCALE, fp16 out [b][h][s][d]       (Q projection)
// MODE 2: RoPE, fp16 out [b][kvh][s][d]                (K projection)
// MODE 3: fp16 out transposed [b][kvh][d][s]           (V projection)
#define GBM 128
#define GBN 128
#define GBK 32
#define LDT 40
#define TILE_E (GBM * LDT)
#define STAGE_E (2 * TILE_E)          // A, B
#define GSM_BYTES (2 * STAGE_E * 2)   // 40960

template <int MODE>
__global__ __launch_bounds__(256, 1)
void gemm_tc(const __half* __restrict__ A, const __half* __restrict__ Bh,
             float* __restrict__ C, __half* __restrict__ OutH,
             const float* __restrict__ fc, int M, int N, int K)
{
    extern __shared__ __half sm[];
    const uint32_t sb = smem_u32(sm);
    const int tid = threadIdx.x;
    const int wid = tid / 32, lane = tid % 32;
    const int warp_m = wid % 4;
    const int warp_n = wid / 4;
    const int m0 = blockIdx.y * GBM, n0 = blockIdx.x * GBN;

    const int ld_row = tid / 4;
    const int ld_col = (tid % 4) * 8;

    const __half* pA  = A  + (size_t)(m0 + ld_row) * K + ld_col;
    const __half* pBh = Bh + (size_t)(n0 + ld_row) * K + ld_col;
    const size_t rstep64 = (size_t)64 * K;

    auto load_chunk = [&](int t, int stg) {
        uint32_t sbase = sb + (uint32_t)(stg * STAGE_E) * 2u;
        uint32_t soff = ((uint32_t)ld_row * LDT + (uint32_t)ld_col) * 2u;
        const int kk = t * GBK;
#pragma unroll
        for (int j = 0; j < 2; j++) {
            uint32_t so = soff + (uint32_t)(j * 64 * LDT) * 2u;
            cp_async16(sbase + 0 * TILE_E * 2 + so, pA  + kk + j * rstep64);
            cp_async16(sbase + 1 * TILE_E * 2 + so, pBh + kk + j * rstep64);
        }
    };

    float acc[2][8][4];
#pragma unroll
    for (int i = 0; i < 2; i++)
#pragma unroll
        for (int j = 0; j < 8; j++)
#pragma unroll
            for (int r = 0; r < 4; r++) acc[i][j][r] = 0.f;

    const int nch = K / GBK;
    load_chunk(0, 0);
    cp_commit();

    for (int t = 0; t < nch; t++) {
        const int stg = t & 1;
        if (t + 1 < nch) {
            load_chunk(t + 1, stg ^ 1);
            cp_commit();
            cp_wait<1>();
        } else {
            cp_wait<0>();
        }
        __syncthreads();

        const uint32_t sbase = sb + (uint32_t)(stg * STAGE_E) * 2u;
#pragma unroll
        for (int ks = 0; ks < 2; ks++) {
            const uint32_t kc = (uint32_t)(ks * 16 + (lane / 16) * 8);
            uint32_t ah[2][4];
#pragma unroll
            for (int mt = 0; mt < 2; mt++) {
                uint32_t row = (uint32_t)(warp_m * 32 + mt * 16 + (lane % 16));
                uint32_t off = (row * LDT + kc) * 2u;
                ldsm_x4(ah[mt], sbase + 0 * TILE_E * 2 + off);
            }
            uint32_t bh[8][2];
#pragma unroll
            for (int ng = 0; ng < 4; ng++) {
                uint32_t row = (uint32_t)(warp_n * 64 + ng * 16 + (lane % 8) +
                                          ((lane / 8) % 2) * 8);
                uint32_t off = (row * LDT + kc) * 2u;
                uint32_t r[4];
                ldsm_x4(r, sbase + 1 * TILE_E * 2 + off);
                bh[2 * ng][0] = r[0]; bh[2 * ng][1] = r[2];
                bh[2 * ng + 1][0] = r[1]; bh[2 * ng + 1][1] = r[3];
            }
#pragma unroll
            for (int mt = 0; mt < 2; mt++)
#pragma unroll
                for (int nt = 0; nt < 8; nt++)
                    mma_f16(acc[mt][nt], ah[mt], bh[nt]);
        }
        __syncthreads();
    }

    // ---------------- fused epilogue ----------------
#pragma unroll
    for (int mt = 0; mt < 2; mt++) {
        int row = m0 + warp_m * 32 + mt * 16 + lane / 4;
#pragma unroll
        for (int nt = 0; nt < 8; nt++) {
            int col = n0 + warp_n * 64 + nt * 8 + (lane % 4) * 2;
            if (MODE == 0) {
                float2 v0 = make_float2(acc[mt][nt][0], acc[mt][nt][1]);
                float2 v1 = make_float2(acc[mt][nt][2], acc[mt][nt][3]);
                *reinterpret_cast<float2*>(&C[(size_t)row * N + col]) = v0;
                *reinterpret_cast<float2*>(&C[(size_t)(row + 8) * N + col]) = v1;
            } else if (MODE == 1 || MODE == 2) {
                const int d = col % D;
                const int hh = col / D;
                const int i = d / 2;
#pragma unroll
                for (int r2 = 0; r2 < 2; r2++) {
                    int rr = row + 8 * r2;
                    int s = rr % S, bb = rr / S;
                    float2 cs = *reinterpret_cast<const float2*>(
                        &fc[((size_t)s * (D / 2) + i) * 2]);
                    float x0 = acc[mt][nt][2 * r2], x1 = acc[mt][nt][2 * r2 + 1];
                    float r0 = x0 * cs.x - x1 * cs.y;
                    float r1 = x0 * cs.y + x1 * cs.x;
                    if (MODE == 1) { r0 *= QK_SCALE; r1 *= QK_SCALE; }
                    size_t o = (MODE == 1)
                        ? ((size_t)(bb * H + hh) * S + s) * D + d
                        : ((size_t)(bb * KVH + hh) * S + s) * D + d;
                    *reinterpret_cast<__half2*>(OutH + o) = __floats2half2_rn(r0, r1);
                }
            } else {  // MODE == 3: V transposed
                const int d = col % D;
                const int kvh = col / D;
#pragma unroll
                for (int r2 = 0; r2 < 2; r2++) {
                    int rr = row + 8 * r2;
                    int s = rr % S, bb = rr / S;
                    size_t ob = ((size_t)(bb * KVH + kvh) * D + d) * S + s;
                    OutH[ob]     = __float2half_rn(acc[mt][nt][2 * r2]);
                    OutH[ob + S] = __float2half_rn(acc[mt][nt][2 * r2 + 1]);
                }
            }
        }
    }
}

// ---------------- tensor-core flash attention (fp16), causal, GQA ----------------
#define AM 128
#define AN 64
#define LQ 136
#define LV 72
#define SQH 0
#define SST 17408                 // start of KV stages (after Q)
#define STSZ 17920                // KH 8704 + VH 9216
#define OVH 8704
#define ATT_SMEM ((SST + 2 * STSZ) * 2)   // 106496 bytes

__global__ __launch_bounds__(256, 1)
void attn_tc(const __half* __restrict__ Qh,
             const __half* __restrict__ Kh,
             const __half* __restrict__ Vh,
             __half* __restrict__ Oh)
{
    extern __shared__ __half sma[];
    const uint32_t sb = smem_u32(sma);
    const int tid = threadIdx.x, wid = tid / 32, lane = tid % 32;
    // LPT scheduling: heaviest q-tiles (largest bx) get the lowest blockIdx.x
    const int bxr = (S / AM - 1) - blockIdx.x;
    const int h = blockIdx.y, b = blockIdx.z;
    const int kvh = h / GROUPS;
    const int q0 = bxr * AM;

    const __half* qhp = Qh + ((size_t)(b * H + h) * S + q0) * D;
    const __half* khp = Kh + (size_t)(b * KVH + kvh) * S * D;
    const __half* vhp = Vh + (size_t)(b * KVH + kvh) * D * S;

    // load Q tile: 128 rows x 128 cols fp16
#pragma unroll
    for (int j = 0; j < 8; j++) {
        int seg = tid + j * 256;            // 0..2047
        int row = seg >> 4, c = (seg & 15) * 8;
        cp_async16(sb + (uint32_t)(SQH + row * LQ + c) * 2, qhp + (size_t)row * D + c);
    }
    cp_commit();

    auto load_kv = [&](int t, int stg) {
        uint32_t sbase = sb + (uint32_t)(SST + stg * STSZ) * 2;
        int kv0 = t * AN;
#pragma unroll
        for (int j = 0; j < 4; j++) {
            int seg = tid + j * 256;        // 0..1023
            int row = seg >> 4, c = (seg & 15) * 8;
            cp_async16(sbase + (uint32_t)(row * LQ + c) * 2,
                       khp + (size_t)(kv0 + row) * D + c);
        }
#pragma unroll
        for (int j = 0; j < 4; j++) {
            int seg = tid + j * 256;
            int row = seg >> 3, c = (seg & 7) * 8;
            cp_async16(sbase + (uint32_t)(OVH + row * LV + c) * 2,
                       vhp + (size_t)row * S + kv0 + c);
        }
    };

    float m0 = -1e30f, m1 = -1e30f, l0 = 0.f, l1 = 0.f;
    float oacc[16][4];
#pragma unroll
    for (int i = 0; i < 16; i++)
#pragma unroll
        for (int j = 0; j < 4; j++) oacc[i][j] = 0.f;

    const int ntiles = 2 * (bxr + 1);
    load_kv(0, 0);
    cp_commit();

    for (int t = 0; t < ntiles; t++) {
        if (t + 1 < ntiles) {
            load_kv(t + 1, (t + 1) & 1);
            cp_commit();
            cp_wait<1>();
        } else {
            cp_wait<0>();
        }
        __syncthreads();
        const uint32_t stg = sb + (uint32_t)(SST + (t & 1) * STSZ) * 2;

        // ---- S = Q K^T (fp16) ----
        float sacc[8][4];
#pragma unroll
        for (int i = 0; i < 8; i++)
#pragma unroll
            for (int j = 0; j < 4; j++) sacc[i][j] = 0.f;

#pragma unroll
        for (int ks = 0; ks < 8; ks++) {
            const uint32_t kc = (uint32_t)(ks * 16 + (lane >> 4) * 8);
            uint32_t ah[4];
            const uint32_t qrow = (uint32_t)(wid * 16 + (lane & 15));
            ldsm_x4(ah, sb + (SQH + qrow * LQ + kc) * 2);
            const uint32_t brow = (uint32_t)((lane & 7) + ((lane >> 3) & 1) * 8);
#pragma unroll
            for (int ng = 0; ng < 4; ng++) {
                uint32_t row = (uint32_t)(ng * 16) + brow;
                uint32_t rh[4];
                ldsm_x4(rh, stg + (row * LQ + kc) * 2);
                uint32_t b0[2] = {rh[0], rh[2]}, b1[2] = {rh[1], rh[3]};
                mma_f16(sacc[2 * ng],     ah, b0);
                mma_f16(sacc[2 * ng + 1], ah, b1);
            }
        }

        // ---- causal mask (only diagonal tiles) ----
        const int row0 = q0 + wid * 16 + (lane >> 2);
        if (t >= 2 * bxr) {
            const int kvb = t * AN + 2 * (lane & 3);
#pragma unroll
            for (int nt = 0; nt < 8; nt++) {
                int col = kvb + nt * 8;
                if (col     > row0)     sacc[nt][0] = -1e30f;
                if (col + 1 > row0)     sacc[nt][1] = -1e30f;
                if (col     > row0 + 8) sacc[nt][2] = -1e30f;
                if (col + 1 > row0 + 8) sacc[nt][3] = -1e30f;
            }
        }

        // ---- online softmax ----
        float mx0 = -1e30f, mx1 = -1e30f;
#pragma unroll
        for (int nt = 0; nt < 8; nt++) {
            mx0 = fmaxf(mx0, fmaxf(sacc[nt][0], sacc[nt][1]));
            mx1 = fmaxf(mx1, fmaxf(sacc[nt][2], sacc[nt][3]));
        }
        mx0 = fmaxf(mx0, __shfl_xor_sync(0xffffffffu, mx0, 1));
        mx0 = fmaxf(mx0, __shfl_xor_sync(0xffffffffu, mx0, 2));
        mx1 = fmaxf(mx1, __shfl_xor_sync(0xffffffffu, mx1, 1));
        mx1 = fmaxf(mx1, __shfl_xor_sync(0xffffffffu, mx1, 2));
        float nm0 = fmaxf(m0, mx0), nm1 = fmaxf(m1, mx1);
        float f0 = __expf(m0 - nm0), f1 = __expf(m1 - nm1);
        float sum0 = 0.f, sum1 = 0.f;
#pragma unroll
        for (int nt = 0; nt < 8; nt++) {
            sacc[nt][0] = __expf(sacc[nt][0] - nm0);
            sacc[nt][1] = __expf(sacc[nt][1] - nm0);
            sacc[nt][2] = __expf(sacc[nt][2] - nm1);
            sacc[nt][3] = __expf(sacc[nt][3] - nm1);
            sum0 += sacc[nt][0] + sacc[nt][1];
            sum1 += sacc[nt][2] + sacc[nt][3];
        }
        sum0 += __shfl_xor_sync(0xffffffffu, sum0, 1);
        sum0 += __shfl_xor_sync(0xffffffffu, sum0, 2);
        sum1 += __shfl_xor_sync(0xffffffffu, sum1, 1);
        sum1 += __shfl_xor_sync(0xffffffffu, sum1, 2);
        l0 = l0 * f0 + sum0;
        l1 = l1 * f1 + sum1;
        m0 = nm0;
        m1 = nm1;
#pragma unroll
        for (int nt = 0; nt < 16; nt++) {
            oacc[nt][0] *= f0;
            oacc[nt][1] *= f0;
            oacc[nt][2] *= f1;
            oacc[nt][3] *= f1;
        }

        // ---- O += P V (fp16 P) ----
#pragma unroll
        for (int ks2 = 0; ks2 < 4; ks2++) {
            const float* ce = sacc[2 * ks2];
            const float* co = sacc[2 * ks2 + 1];
            uint32_t ph[4];
            __half2 t0 = __floats2half2_rn(ce[0], ce[1]);
            __half2 t1 = __floats2half2_rn(ce[2], ce[3]);
            __half2 t2 = __floats2half2_rn(co[0], co[1]);
            __half2 t3 = __floats2half2_rn(co[2], co[3]);
            ph[0] = *reinterpret_cast<uint32_t*>(&t0);
            ph[1] = *reinterpret_cast<uint32_t*>(&t1);
            ph[2] = *reinterpret_cast<uint32_t*>(&t2);
            ph[3] = *reinterpret_cast<uint32_t*>(&t3);
            const uint32_t kc2 = (uint32_t)(ks2 * 16 + (lane >> 4) * 8);
            const uint32_t brow = (uint32_t)((lane & 7) + ((lane >> 3) & 1) * 8);
#pragma unroll
            for (int ng = 0; ng < 8; ng++) {
                uint32_t row = (uint32_t)(ng * 16) + brow;
                uint32_t rh[4];
                ldsm_x4(rh, stg + (OVH + row * LV + kc2) * 2);
                uint32_t b0[2] = {rh[0], rh[2]}, b1[2] = {rh[1], rh[3]};
                mma_f16(oacc[2 * ng],     ph, b0);
                mma_f16(oacc[2 * ng + 1], ph, b1);
            }
        }
        __syncthreads();
    }

    // ---- epilogue: normalize, store fp16 O in [b,s,h,d] ----
    const float inv0 = 1.f / l0, inv1 = 1.f / l1;
    const int row0 = q0 + wid * 16 + (lane >> 2);
#pragma unroll
    for (int nt = 0; nt < 16; nt++) {
        int col = nt * 8 + 2 * (lane & 3);
        size_t o0 = ((size_t)(b * S + row0) * H + h) * D + col;
        size_t o1 = ((size_t)(b * S + row0 + 8) * H + h) * D + col;
        *reinterpret_cast<__half2*>(Oh + o0) =
            __floats2half2_rn(oacc[nt][0] * inv0, oacc[nt][1] * inv0);
        *reinterpret_cast<__half2*>(Oh + o1) =
            __floats2half2_rn(oacc[nt][2] * inv1, oacc[nt][3] * inv1);
    }
}

// ---------------- host ----------------
extern "C" void kernel_launch(void* const* d_in, const int* in_sizes, int n_in,
                              void* d_out, int out_size)
{
    const float* x  = (const float*)d_in[0];
    const float* fc = (const float*)d_in[1];
    const float* wq = (const float*)d_in[2];
    const float* wk = (const float*)d_in[3];
    const float* wv = (const float*)d_in[4];
    const float* wo = (const float*)d_in[5];
    float* out = (float*)d_out;

    __half *xa_h, *oa_h;
    __half *wqT_h, *wkT_h, *wvT_h, *woT_h;
    __half *qs_h, *ks_h, *vt_h;
    cudaGetSymbolAddress((void**)&xa_h, g_xa_h);
    cudaGetSymbolAddress((void**)&oa_h, g_oa_h);
    cudaGetSymbolAddress((void**)&wqT_h, g_wqT_h);
    cudaGetSymbolAddress((void**)&wkT_h, g_wkT_h);
    cudaGetSymbolAddress((void**)&wvT_h, g_wvT_h);
    cudaGetSymbolAddress((void**)&woT_h, g_woT_h);
    cudaGetSymbolAddress((void**)&qs_h, g_qs_h);
    cudaGetSymbolAddress((void**)&ks_h, g_ks_h);
    cudaGetSymbolAddress((void**)&vt_h, g_vt_h);

    cudaFuncSetAttribute(gemm_tc<0>, cudaFuncAttributeMaxDynamicSharedMemorySize, GSM_BYTES);
    cudaFuncSetAttribute(gemm_tc<1>, cudaFuncAttributeMaxDynamicSharedMemorySize, GSM_BYTES);
    cudaFuncSetAttribute(gemm_tc<2>, cudaFuncAttributeMaxDynamicSharedMemorySize, GSM_BYTES);
    cudaFuncSetAttribute(gemm_tc<3>, cudaFuncAttributeMaxDynamicSharedMemorySize, GSM_BYTES);
    cudaFuncSetAttribute(attn_tc, cudaFuncAttributeMaxDynamicSharedMemorySize, ATT_SMEM);

    // x -> fp16
    {
        int n4 = MROWS * HID / 4;
        to_f16<<<(n4 + 255) / 256, 256>>>((const float4*)x, (__half2*)xa_h, n4);
    }
    // transpose weights (fp16)
    {
        dim3 blk(32, 8);
        transpose_h<<<dim3(ND_Q / 32, HID / 32), blk>>>(wq, wqT_h, HID, ND_Q);
        transpose_h<<<dim3(ND_KV / 32, HID / 32), blk>>>(wk, wkT_h, HID, ND_KV);
        transpose_h<<<dim3(ND_KV / 32, HID / 32), blk>>>(wv, wvT_h, HID, ND_KV);
        transpose_h<<<dim3(ND_Q / 32, ND_Q / 32), blk>>>(wo, woT_h, ND_Q, HID);
    }
    // QKV projections with fused RoPE/relayout epilogues
    {
        gemm_tc<1><<<dim3(ND_Q / GBN, MROWS / GBM), 256, GSM_BYTES>>>(
            xa_h, wqT_h, nullptr, qs_h, fc, MROWS, ND_Q, HID);
        gemm_tc<2><<<dim3(ND_KV / GBN, MROWS / GBM), 256, GSM_BYTES>>>(
            xa_h, wkT_h, nullptr, ks_h, fc, MROWS, ND_KV, HID);
        gemm_tc<3><<<dim3(ND_KV / GBN, MROWS / GBM), 256, GSM_BYTES>>>(
            xa_h, wvT_h, nullptr, vt_h, nullptr, MROWS, ND_KV, HID);
    }
    // tensor-core flash attention (fp16, LPT-ordered)
    {
        dim3 grid(S / AM, H, B);
        attn_tc<<<grid, 256, ATT_SMEM>>>(qs_h, ks_h, vt_h, oa_h);
    }
    // output projection (fp16 tensor cores, fp32 out)
    {
        gemm_tc<0><<<dim3(HID / GBN, MROWS / GBM), 256, GSM_BYTES>>>(
            oa_h, woT_h, out, nullptr, nullptr, MROWS, HID, ND_Q);
    }
}

// round 16
// speedup vs baseline: 1.0233x; 1.0233x over previous
#include <cuda_runtime.h>
#include <cuda_bf16.h>
#include <cuda_fp16.h>
#include <cstdint>

#define B 2
#define S 2048
#define HID 2048
#define H 16
#define KVH 4
#define D 128
#define GROUPS (H / KVH)
#define MROWS (B * S)          // 4096
#define ND_Q (H * D)           // 2048
#define ND_KV (KVH * D)        // 512
#define QK_SCALE 0.08838834764831845f

// ---------------- scratch (no allocations allowed) ----------------
__device__ float g_q[MROWS * H * D];
__device__ float g_k[MROWS * KVH * D];
__device__ float g_v[MROWS * KVH * D];

__device__ __align__(16) __half g_xa_h[MROWS * HID];      // x as fp16
__device__ __align__(16) __half g_oa_h[MROWS * ND_Q];     // attention out as fp16
__device__ __align__(16) __half g_wqT_h[ND_Q * HID];
__device__ __align__(16) __half g_wkT_h[ND_KV * HID];
__device__ __align__(16) __half g_wvT_h[ND_KV * HID];
__device__ __align__(16) __half g_woT_h[HID * ND_Q];
// attention operand layouts (fp16)
__device__ __align__(16) __half g_qs_h[B * H * S * D];    // [b][h][s][d], scaled
__device__ __align__(16) __half g_ks_h[B * KVH * S * D];  // [b][kvh][s][d]
__device__ __align__(16) __half g_vt_h[B * KVH * D * S];  // [b][kvh][d][s]

// ---------------- helpers ----------------
__device__ __forceinline__ uint32_t smem_u32(const void* p) {
    uint32_t a;
    asm("{ .reg .u64 t; cvta.to.shared.u64 t, %1; cvt.u32.u64 %0, t; }" : "=r"(a) : "l"(p));
    return a;
}
__device__ __forceinline__ void cp_async16(uint32_t saddr, const void* gaddr) {
    asm volatile("cp.async.cg.shared.global [%0], [%1], 16;" :: "r"(saddr), "l"(gaddr)
                 : "memory");
}
__device__ __forceinline__ void cp_commit() {
    asm volatile("cp.async.commit_group;" ::: "memory");
}
template <int N>
__device__ __forceinline__ void cp_wait() {
    asm volatile("cp.async.wait_group %0;" :: "n"(N) : "memory");
}
__device__ __forceinline__ void ldsm_x4(uint32_t* r, uint32_t addr) {
    asm volatile("ldmatrix.sync.aligned.m8n8.x4.shared.b16 {%0,%1,%2,%3}, [%4];"
                 : "=r"(r[0]), "=r"(r[1]), "=r"(r[2]), "=r"(r[3]) : "r"(addr));
}
__device__ __forceinline__ void mma_f16(float* c, const uint32_t* a, const uint32_t* b) {
    asm volatile(
        "mma.sync.aligned.m16n8k16.row.col.f32.f16.f16.f32 "
        "{%0,%1,%2,%3}, {%4,%5,%6,%7}, {%8,%9}, {%0,%1,%2,%3};"
        : "+f"(c[0]), "+f"(c[1]), "+f"(c[2]), "+f"(c[3])
        : "r"(a[0]), "r"(a[1]), "r"(a[2]), "r"(a[3]), "r"(b[0]), "r"(b[1]));
}

// ---------------- fp32 -> fp16 convert ----------------
__global__ void to_f16(const float4* __restrict__ src, __half2* __restrict__ dst, int n4) {
    int i = blockIdx.x * blockDim.x + threadIdx.x;
    if (i >= n4) return;
    float4 v = src[i];
    dst[2 * i]     = __floats2half2_rn(v.x, v.y);
    dst[2 * i + 1] = __floats2half2_rn(v.z, v.w);
}

// ---------------- transpose: W[K,N] fp32 -> T[N,K] fp16 ----------------
__global__ void transpose_h(const float* __restrict__ W, __half* __restrict__ Th,
                            int K, int N) {
    __shared__ float t[32][33];
    int k0 = blockIdx.y * 32, n0 = blockIdx.x * 32;
    int tx = threadIdx.x, ty = threadIdx.y;
#pragma unroll
    for (int j = 0; j < 4; j++)
        t[ty + j * 8][tx] = W[(size_t)(k0 + ty + j * 8) * N + n0 + tx];
    __syncthreads();
#pragma unroll
    for (int j = 0; j < 4; j++) {
        int n = n0 + ty + j * 8;
        Th[(size_t)n * K + k0 + tx] = __float2half_rn(t[tx][ty + j * 8]);
    }
}

// ---------------- fp16 tensor-core GEMM: C = A @ Th^T ----------------
#define GBM 128
#define GBN 128
#define GBK 32
#define LDT 40
#define TILE_E (GBM * LDT)
#define STAGE_E (2 * TILE_E)          // A, B
#define GSM_BYTES (2 * STAGE_E * 2)   // 40960

__global__ __launch_bounds__(256, 1)
void gemm_tc(const __half* __restrict__ A, const __half* __restrict__ Bh,
             float* __restrict__ C, int M, int N, int K)
{
    extern __shared__ __half sm[];
    const uint32_t sb = smem_u32(sm);
    const int tid = threadIdx.x;
    const int wid = tid / 32, lane = tid % 32;
    const int warp_m = wid % 4;
    const int warp_n = wid / 4;
    const int m0 = blockIdx.y * GBM, n0 = blockIdx.x * GBN;

    const int ld_row = tid / 4;
    const int ld_col = (tid % 4) * 8;

    const __half* pA  = A  + (size_t)(m0 + ld_row) * K + ld_col;
    const __half* pBh = Bh + (size_t)(n0 + ld_row) * K + ld_col;
    const size_t rstep64 = (size_t)64 * K;

    auto load_chunk = [&](int t, int stg) {
        uint32_t sbase = sb + (uint32_t)(stg * STAGE_E) * 2u;
        uint32_t soff = ((uint32_t)ld_row * LDT + (uint32_t)ld_col) * 2u;
        const int kk = t * GBK;
#pragma unroll
        for (int j = 0; j < 2; j++) {
            uint32_t so = soff + (uint32_t)(j * 64 * LDT) * 2u;
            cp_async16(sbase + 0 * TILE_E * 2 + so, pA  + kk + j * rstep64);
            cp_async16(sbase + 1 * TILE_E * 2 + so, pBh + kk + j * rstep64);
        }
    };

    float acc[2][8][4];
#pragma unroll
    for (int i = 0; i < 2; i++)
#pragma unroll
        for (int j = 0; j < 8; j++)
#pragma unroll
            for (int r = 0; r < 4; r++) acc[i][j][r] = 0.f;

    const int nch = K / GBK;
    load_chunk(0, 0);
    cp_commit();

    for (int t = 0; t < nch; t++) {
        const int stg = t & 1;
        if (t + 1 < nch) {
            load_chunk(t + 1, stg ^ 1);
            cp_commit();
            cp_wait<1>();
        } else {
            cp_wait<0>();
        }
        __syncthreads();

        const uint32_t sbase = sb + (uint32_t)(stg * STAGE_E) * 2u;
#pragma unroll
        for (int ks = 0; ks < 2; ks++) {
            const uint32_t kc = (uint32_t)(ks * 16 + (lane / 16) * 8);
            uint32_t ah[2][4];
#pragma unroll
            for (int mt = 0; mt < 2; mt++) {
                uint32_t row = (uint32_t)(warp_m * 32 + mt * 16 + (lane % 16));
                uint32_t off = (row * LDT + kc) * 2u;
                ldsm_x4(ah[mt], sbase + 0 * TILE_E * 2 + off);
            }
            uint32_t bh[8][2];
#pragma unroll
            for (int ng = 0; ng < 4; ng++) {
                uint32_t row = (uint32_t)(warp_n * 64 + ng * 16 + (lane % 8) +
                                          ((lane / 8) % 2) * 8);
                uint32_t off = (row * LDT + kc) * 2u;
                uint32_t r[4];
                ldsm_x4(r, sbase + 1 * TILE_E * 2 + off);
                bh[2 * ng][0] = r[0]; bh[2 * ng][1] = r[2];
                bh[2 * ng + 1][0] = r[1]; bh[2 * ng + 1][1] = r[3];
            }
#pragma unroll
            for (int mt = 0; mt < 2; mt++)
#pragma unroll
                for (int nt = 0; nt < 8; nt++)
                    mma_f16(acc[mt][nt], ah[mt], bh[nt]);
        }
        __syncthreads();
    }

#pragma unroll
    for (int mt = 0; mt < 2; mt++) {
        int row = m0 + warp_m * 32 + mt * 16 + lane / 4;
#pragma unroll
        for (int nt = 0; nt < 8; nt++) {
            int col = n0 + warp_n * 64 + nt * 8 + (lane % 4) * 2;
            float2 v0 = make_float2(acc[mt][nt][0], acc[mt][nt][1]);
            float2 v1 = make_float2(acc[mt][nt][2], acc[mt][nt][3]);
            *reinterpret_cast<float2*>(&C[(size_t)row * N + col]) = v0;
            *reinterpret_cast<float2*>(&C[(size_t)(row + 8) * N + col]) = v1;
        }
    }
}

// -------- RoPE + scale, Q: [b,s,h,d] f32 -> [b,h,s,d] fp16 --------
__global__ void rope_q_f16(const float* __restrict__ q, const float* __restrict__ fc,
                           __half* __restrict__ qh) {
    int idx = blockIdx.x * blockDim.x + threadIdx.x;
    if (idx >= B * H * S * (D / 2)) return;
    int i = idx % (D / 2);
    int s = (idx / (D / 2)) % S;
    int h = (idx / (D / 2) / S) % H;
    int b = idx / (D / 2) / S / H;
    float c  = fc[(s * (D / 2) + i) * 2 + 0];
    float sn = fc[(s * (D / 2) + i) * 2 + 1];
    const float* p = q + ((size_t)(b * S + s) * H + h) * D + 2 * i;
    float x0 = p[0], x1 = p[1];
    float r0 = (x0 * c - x1 * sn) * QK_SCALE;
    float r1 = (x0 * sn + x1 * c) * QK_SCALE;
    size_t o = ((size_t)(b * H + h) * S + s) * D + 2 * i;
    *reinterpret_cast<__half2*>(qh + o) = __floats2half2_rn(r0, r1);
}

// -------- RoPE, K: [b,s,kvh,d] f32 -> [b,kvh,s,d] fp16 --------
__global__ void rope_k_f16(const float* __restrict__ k, const float* __restrict__ fc,
                           __half* __restrict__ kh) {
    int idx = blockIdx.x * blockDim.x + threadIdx.x;
    if (idx >= B * KVH * S * (D / 2)) return;
    int i = idx % (D / 2);
    int s = (idx / (D / 2)) % S;
    int h = (idx / (D / 2) / S) % KVH;
    int b = idx / (D / 2) / S / KVH;
    float c  = fc[(s * (D / 2) + i) * 2 + 0];
    float sn = fc[(s * (D / 2) + i) * 2 + 1];
    const float* p = k + ((size_t)(b * S + s) * KVH + h) * D + 2 * i;
    float x0 = p[0], x1 = p[1];
    float r0 = x0 * c - x1 * sn;
    float r1 = x0 * sn + x1 * c;
    size_t o = ((size_t)(b * KVH + h) * S + s) * D + 2 * i;
    *reinterpret_cast<__half2*>(kh + o) = __floats2half2_rn(r0, r1);
}

// -------- V transpose: [b,s,kvh,d] f32 -> [b,kvh,d,s] fp16 --------
__global__ void v_t_f16(const float* __restrict__ v, __half* __restrict__ vh) {
    __shared__ float t[32][33];
    int d0 = blockIdx.x * 32, s0 = blockIdx.y * 32;
    int bk = blockIdx.z;
    int b = bk / KVH, kvh = bk % KVH;
    int tx = threadIdx.x, ty = threadIdx.y;
#pragma unroll
    for (int j = 0; j < 4; j++)
        t[ty + j * 8][tx] = v[((size_t)(b * S + s0 + ty + j * 8) * KVH + kvh) * D + d0 + tx];
    __syncthreads();
#pragma unroll
    for (int j = 0; j < 4; j++) {
        int d = d0 + ty + j * 8;
        size_t o = ((size_t)(b * KVH + kvh) * D + d) * S + s0 + tx;
        vh[o] = __float2half_rn(t[tx][ty + j * 8]);
    }
}

// ---------------- tensor-core flash attention (fp16), causal, GQA ----------------
#define AM 128
#define AN 64
#define LQ 136
#define LV 72
#define SQH 0
#define SST 17408                 // start of KV stages (after Q)
#define STSZ 17920                // KH 8704 + VH 9216
#define OVH 8704
#define ATT_SMEM ((SST + 2 * STSZ) * 2)   // 106496 bytes

__global__ __launch_bounds__(256, 1)
void attn_tc(const __half* __restrict__ Qh,
             const __half* __restrict__ Kh,
             const __half* __restrict__ Vh,
             __half* __restrict__ Oh)
{
    extern __shared__ __half sma[];
    const uint32_t sb = smem_u32(sma);
    const int tid = threadIdx.x, wid = tid / 32, lane = tid % 32;
    // LPT scheduling: heaviest q-tiles (most KV tiles) get the lowest blockIdx.x
    const int bxr = (S / AM - 1) - blockIdx.x;
    const int h = blockIdx.y, b = blockIdx.z;
    const int kvh = h / GROUPS;
    const int q0 = bxr * AM;

    const __half* qhp = Qh + ((size_t)(b * H + h) * S + q0) * D;
    const __half* khp = Kh + (size_t)(b * KVH + kvh) * S * D;
    const __half* vhp = Vh + (size_t)(b * KVH + kvh) * D * S;

    // load Q tile: 128 rows x 128 cols fp16
#pragma unroll
    for (int j = 0; j < 8; j++) {
        int seg = tid + j * 256;            // 0..2047
        int row = seg >> 4, c = (seg & 15) * 8;
        cp_async16(sb + (uint32_t)(SQH + row * LQ + c) * 2, qhp + (size_t)row * D + c);
    }
    cp_commit();

    auto load_kv = [&](int t, int stg) {
        uint32_t sbase = sb + (uint32_t)(SST + stg * STSZ) * 2;
        int kv0 = t * AN;
#pragma unroll
        for (int j = 0; j < 4; j++) {
            int seg = tid + j * 256;        // 0..1023
            int row = seg >> 4, c = (seg & 15) * 8;
            cp_async16(sbase + (uint32_t)(row * LQ + c) * 2,
                       khp + (size_t)(kv0 + row) * D + c);
        }
#pragma unroll
        for (int j = 0; j < 4; j++) {
            int seg = tid + j * 256;
            int row = seg >> 3, c = (seg & 7) * 8;
            cp_async16(sbase + (uint32_t)(OVH + row * LV + c) * 2,
                       vhp + (size_t)row * S + kv0 + c);
        }
    };

    float m0 = -1e30f, m1 = -1e30f, l0 = 0.f, l1 = 0.f;
    float oacc[16][4];
#pragma unroll
    for (int i = 0; i < 16; i++)
#pragma unroll
        for (int j = 0; j < 4; j++) oacc[i][j] = 0.f;

    const int ntiles = 2 * (bxr + 1);
    load_kv(0, 0);
    cp_commit();

    for (int t = 0; t < ntiles; t++) {
        if (t + 1 < ntiles) {
            load_kv(t + 1, (t + 1) & 1);
            cp_commit();
            cp_wait<1>();
        } else {
            cp_wait<0>();
        }
        __syncthreads();
        const uint32_t stg = sb + (uint32_t)(SST + (t & 1) * STSZ) * 2;

        // ---- S = Q K^T (fp16) ----
        float sacc[8][4];
#pragma unroll
        for (int i = 0; i < 8; i++)
#pragma unroll
            for (int j = 0; j < 4; j++) sacc[i][j] = 0.f;

#pragma unroll
        for (int ks = 0; ks < 8; ks++) {
            const uint32_t kc = (uint32_t)(ks * 16 + (lane >> 4) * 8);
            uint32_t ah[4];
            const uint32_t qrow = (uint32_t)(wid * 16 + (lane & 15));
            ldsm_x4(ah, sb + (SQH + qrow * LQ + kc) * 2);
            const uint32_t brow = (uint32_t)((lane & 7) + ((lane >> 3) & 1) * 8);
#pragma unroll
            for (int ng = 0; ng < 4; ng++) {
                uint32_t row = (uint32_t)(ng * 16) + brow;
                uint32_t rh[4];
                ldsm_x4(rh, stg + (row * LQ + kc) * 2);
                uint32_t b0[2] = {rh[0], rh[2]}, b1[2] = {rh[1], rh[3]};
                mma_f16(sacc[2 * ng],     ah, b0);
                mma_f16(sacc[2 * ng + 1], ah, b1);
            }
        }

        // ---- causal mask (only diagonal tiles) ----
        const int row0 = q0 + wid * 16 + (lane >> 2);
        if (t >= 2 * bxr) {
            const int kvb = t * AN + 2 * (lane & 3);
#pragma unroll
            for (int nt = 0; nt < 8; nt++) {
                int col = kvb + nt * 8;
                if (col     > row0)     sacc[nt][0] = -1e30f;
                if (col + 1 > row0)     sacc[nt][1] = -1e30f;
                if (col     > row0 + 8) sacc[nt][2] = -1e30f;
                if (col + 1 > row0 + 8) sacc[nt][3] = -1e30f;
            }
        }

        // ---- online softmax ----
        float mx0 = -1e30f, mx1 = -1e30f;
#pragma unroll
        for (int nt = 0; nt < 8; nt++) {
            mx0 = fmaxf(mx0, fmaxf(sacc[nt][0], sacc[nt][1]));
            mx1 = fmaxf(mx1, fmaxf(sacc[nt][2], sacc[nt][3]));
        }
        mx0 = fmaxf(mx0, __shfl_xor_sync(0xffffffffu, mx0, 1));
        mx0 = fmaxf(mx0, __shfl_xor_sync(0xffffffffu, mx0, 2));
        mx1 = fmaxf(mx1, __shfl_xor_sync(0xffffffffu, mx1, 1));
        mx1 = fmaxf(mx1, __shfl_xor_sync(0xffffffffu, mx1, 2));
        float nm0 = fmaxf(m0, mx0), nm1 = fmaxf(m1, mx1);
        float f0 = __expf(m0 - nm0), f1 = __expf(m1 - nm1);
        float sum0 = 0.f, sum1 = 0.f;
#pragma unroll
        for (int nt = 0; nt < 8; nt++) {
            sacc[nt][0] = __expf(sacc[nt][0] - nm0);
            sacc[nt][1] = __expf(sacc[nt][1] - nm0);
            sacc[nt][2] = __expf(sacc[nt][2] - nm1);
            sacc[nt][3] = __expf(sacc[nt][3] - nm1);
            sum0 += sacc[nt][0] + sacc[nt][1];
            sum1 += sacc[nt][2] + sacc[nt][3];
        }
        sum0 += __shfl_xor_sync(0xffffffffu, sum0, 1);
        sum0 += __shfl_xor_sync(0xffffffffu, sum0, 2);
        sum1 += __shfl_xor_sync(0xffffffffu, sum1, 1);
        sum1 += __shfl_xor_sync(0xffffffffu, sum1, 2);
        l0 = l0 * f0 + sum0;
        l1 = l1 * f1 + sum1;
        m0 = nm0;
        m1 = nm1;
#pragma unroll
        for (int nt = 0; nt < 16; nt++) {
            oacc[nt][0] *= f0;
            oacc[nt][1] *= f0;
            oacc[nt][2] *= f1;
            oacc[nt][3] *= f1;
        }

        // ---- O += P V (fp16 P) ----
#pragma unroll
        for (int ks2 = 0; ks2 < 4; ks2++) {
            const float* ce = sacc[2 * ks2];
            const float* co = sacc[2 * ks2 + 1];
            uint32_t ph[4];
            __half2 t0 = __floats2half2_rn(ce[0], ce[1]);
            __half2 t1 = __floats2half2_rn(ce[2], ce[3]);
            __half2 t2 = __floats2half2_rn(co[0], co[1]);
            __half2 t3 = __floats2half2_rn(co[2], co[3]);
            ph[0] = *reinterpret_cast<uint32_t*>(&t0);
            ph[1] = *reinterpret_cast<uint32_t*>(&t1);
            ph[2] = *reinterpret_cast<uint32_t*>(&t2);
            ph[3] = *reinterpret_cast<uint32_t*>(&t3);
            const uint32_t kc2 = (uint32_t)(ks2 * 16 + (lane >> 4) * 8);
            const uint32_t brow = (uint32_t)((lane & 7) + ((lane >> 3) & 1) * 8);
#pragma unroll
            for (int ng = 0; ng < 8; ng++) {
                uint32_t row = (uint32_t)(ng * 16) + brow;
                uint32_t rh[4];
                ldsm_x4(rh, stg + (OVH + row * LV + kc2) * 2);
                uint32_t b0[2] = {rh[0], rh[2]}, b1[2] = {rh[1], rh[3]};
                mma_f16(oacc[2 * ng],     ph, b0);
                mma_f16(oacc[2 * ng + 1], ph, b1);
            }
        }
        __syncthreads();
    }

    // ---- epilogue: normalize, store fp16 O in [b,s,h,d] ----
    const float inv0 = 1.f / l0, inv1 = 1.f / l1;
    const int row0 = q0 + wid * 16 + (lane >> 2);
#pragma unroll
    for (int nt = 0; nt < 16; nt++) {
        int col = nt * 8 + 2 * (lane & 3);
        size_t o0 = ((size_t)(b * S + row0) * H + h) * D + col;
        size_t o1 = ((size_t)(b * S + row0 + 8) * H + h) * D + col;
        *reinterpret_cast<__half2*>(Oh + o0) =
            __floats2half2_rn(oacc[nt][0] * inv0, oacc[nt][1] * inv0);
        *reinterpret_cast<__half2*>(Oh + o1) =
            __floats2half2_rn(oacc[nt][2] * inv1, oacc[nt][3] * inv1);
    }
}

// ---------------- host ----------------
extern "C" void kernel_launch(void* const* d_in, const int* in_sizes, int n_in,
                              void* d_out, int out_size)
{
    const float* x  = (const float*)d_in[0];
    const float* fc = (const float*)d_in[1];
    const float* wq = (const float*)d_in[2];
    const float* wk = (const float*)d_in[3];
    const float* wv = (const float*)d_in[4];
    const float* wo = (const float*)d_in[5];
    float* out = (float*)d_out;

    float *pq, *pk, *pv;
    cudaGetSymbolAddress((void**)&pq, g_q);
    cudaGetSymbolAddress((void**)&pk, g_k);
    cudaGetSymbolAddress((void**)&pv, g_v);
    __half *xa_h, *oa_h;
    __half *wqT_h, *wkT_h, *wvT_h, *woT_h;
    __half *qs_h, *ks_h, *vt_h;
    cudaGetSymbolAddress((void**)&xa_h, g_xa_h);
    cudaGetSymbolAddress((void**)&oa_h, g_oa_h);
    cudaGetSymbolAddress((void**)&wqT_h, g_wqT_h);
    cudaGetSymbolAddress((void**)&wkT_h, g_wkT_h);
    cudaGetSymbolAddress((void**)&wvT_h, g_wvT_h);
    cudaGetSymbolAddress((void**)&woT_h, g_woT_h);
    cudaGetSymbolAddress((void**)&qs_h, g_qs_h);
    cudaGetSymbolAddress((void**)&ks_h, g_ks_h);
    cudaGetSymbolAddress((void**)&vt_h, g_vt_h);

    cudaFuncSetAttribute(gemm_tc, cudaFuncAttributeMaxDynamicSharedMemorySize, GSM_BYTES);
    cudaFuncSetAttribute(attn_tc, cudaFuncAttributeMaxDynamicSharedMemorySize, ATT_SMEM);

    // x -> fp16
    {
        int n4 = MROWS * HID / 4;
        to_f16<<<(n4 + 255) / 256, 256>>>((const float4*)x, (__half2*)xa_h, n4);
    }
    // transpose weights (fp16)
    {
        dim3 blk(32, 8);
        transpose_h<<<dim3(ND_Q / 32, HID / 32), blk>>>(wq, wqT_h, HID, ND_Q);
        transpose_h<<<dim3(ND_KV / 32, HID / 32), blk>>>(wk, wkT_h, HID, ND_KV);
        transpose_h<<<dim3(ND_KV / 32, HID / 32), blk>>>(wv, wvT_h, HID, ND_KV);
        transpose_h<<<dim3(ND_Q / 32, ND_Q / 32), blk>>>(wo, woT_h, ND_Q, HID);
    }
    // QKV projections (fp16 tensor cores)
    {
        gemm_tc<<<dim3(ND_Q / GBN, MROWS / GBM), 256, GSM_BYTES>>>(
            xa_h, wqT_h, pq, MROWS, ND_Q, HID);
        gemm_tc<<<dim3(ND_KV / GBN, MROWS / GBM), 256, GSM_BYTES>>>(
            xa_h, wkT_h, pk, MROWS, ND_KV, HID);
        gemm_tc<<<dim3(ND_KV / GBN, MROWS / GBM), 256, GSM_BYTES>>>(
            xa_h, wvT_h, pv, MROWS, ND_KV, HID);
    }
    // RoPE + relayout for attention (fp16)
    {
        int nq = B * H * S * (D / 2);
        rope_q_f16<<<(nq + 255) / 256, 256>>>(pq, fc, qs_h);
        int nk = B * KVH * S * (D / 2);
        rope_k_f16<<<(nk + 255) / 256, 256>>>(pk, fc, ks_h);
        dim3 blk(32, 8);
        v_t_f16<<<dim3(D / 32, S / 32, B * KVH), blk>>>(pv, vt_h);
    }
    // tensor-core flash attention (fp16, LPT-ordered)
    {
        dim3 grid(S / AM, H, B);
        attn_tc<<<grid, 256, ATT_SMEM>>>(qs_h, ks_h, vt_h, oa_h);
    }
    // output projection (fp16 tensor cores)
    {
        gemm_tc<<<dim3(HID / GBN, MROWS / GBM), 256, GSM_BYTES>>>(
            oa_h, woT_h, out, MROWS, HID, ND_Q);
    }
}